// round 3
// baseline (speedup 1.0000x reference)
#include <cuda_runtime.h>

#define N_BASES 5
#define C_IN    128
#define C_OUT   128
#define HW      56
#define BATCH   32
#define WELEMS  (C_OUT * C_IN * 9)      // 147456 per base
#define XS_STRIDE 12                    // padded row stride (bank-conflict-free)
#define CI_HALF 64                      // channels per smem stage
#define KC      8                       // k-steps (input channels) per weight chunk
#define WCHUNK  (KC * C_OUT * 2)        // 2048 floats = 8 KB per buffer

// -------- device scratch (no allocations allowed) --------
__device__ float g_m[N_BASES];
__device__ float g_weff[9 * C_IN * C_OUT * 2];   // [kidx][cin][cout][2], value duplicated

// -------- packed f32x2 helpers --------
__device__ __forceinline__ void ffma2(unsigned long long& d, unsigned long long a,
                                      unsigned long long b) {
    asm("fma.rn.f32x2 %0, %1, %2, %0;" : "+l"(d) : "l"(a), "l"(b));
}
__device__ __forceinline__ unsigned long long pack2(float a, float b) {
    unsigned long long r;
    asm("mov.b64 %0, {%1, %2};" : "=l"(r) : "r"(__float_as_int(a)), "r"(__float_as_int(b)));
    return r;
}
__device__ __forceinline__ void unpack2(unsigned long long v, float& a, float& b) {
    int lo, hi;
    asm("mov.b64 {%0, %1}, %2;" : "=r"(lo), "=r"(hi) : "l"(v));
    a = __int_as_float(lo);
    b = __int_as_float(hi);
}

// ================= kernel 1: per-base mean(|w|) =================
__global__ void mean_abs_kernel(const float* __restrict__ w) {
    int n = blockIdx.x;
    const float* wn = w + (size_t)n * WELEMS;
    float s = 0.f;
    for (int i = threadIdx.x; i < WELEMS; i += 256) s += fabsf(wn[i]);
    __shared__ float red[256];
    red[threadIdx.x] = s;
    __syncthreads();
    for (int off = 128; off > 0; off >>= 1) {
        if (threadIdx.x < off) red[threadIdx.x] += red[threadIdx.x + off];
        __syncthreads();
    }
    if (threadIdx.x == 0) g_m[n] = red[0] / (float)WELEMS;
}

// ================= kernel 2: effective weight, duplicated pairs =================
// g_weff[((kidx*C_IN + i)*C_OUT + o)*2 + {0,1}] = sum_n scales[n]*m[n]*sign(w[n,o,i,kidx])
__global__ void build_weff_kernel(const float* __restrict__ w,
                                  const float* __restrict__ scales) {
    int idx = blockIdx.x * blockDim.x + threadIdx.x;  // idx = (kidx*C_IN + i)*C_OUT + o
    if (idx >= WELEMS) return;
    int o = idx % C_OUT;
    int t = idx / C_OUT;
    int i = t % C_IN;
    int kidx = t / C_IN;
    float v = 0.f;
#pragma unroll
    for (int n = 0; n < N_BASES; n++) {
        float wv = w[(((size_t)n * C_OUT + o) * C_IN + i) * 9 + kidx];
        float sg = (wv > 0.f) ? 1.f : ((wv < 0.f) ? -1.f : 0.f);
        v += scales[n] * g_m[n] * sg;
    }
    g_weff[idx * 2 + 0] = v;
    g_weff[idx * 2 + 1] = v;
}

// ================= conv kernel =================
__device__ __forceinline__ void issue_chunk(float* sdst_base, const float* gsrc_base,
                                            int tid) {
    unsigned sdst = (unsigned)__cvta_generic_to_shared(sdst_base) + (unsigned)tid * 16u;
    const float* gsrc = gsrc_base + tid * 4;
#pragma unroll
    for (int j = 0; j < 4; j++) {
        asm volatile("cp.async.cg.shared.global [%0], [%1], 16;" ::"r"(sdst + j * 2048u),
                     "l"(gsrc + j * 512));
    }
    asm volatile("cp.async.commit_group;" ::: "memory");
}

__device__ __forceinline__ void fma_tile(unsigned long long* acc, unsigned long long x0,
                                         unsigned long long x1, unsigned long long x2,
                                         unsigned long long x3, const float* wb) {
    ulonglong2 w01 = *(const ulonglong2*)(wb + 0);
    ulonglong2 w23 = *(const ulonglong2*)(wb + 4);
    ulonglong2 w45 = *(const ulonglong2*)(wb + 8);
    ulonglong2 w67 = *(const ulonglong2*)(wb + 12);
    ffma2(acc[0], x0, w01.x);  ffma2(acc[1], x1, w01.x);
    ffma2(acc[2], x2, w01.x);  ffma2(acc[3], x3, w01.x);
    ffma2(acc[4], x0, w01.y);  ffma2(acc[5], x1, w01.y);
    ffma2(acc[6], x2, w01.y);  ffma2(acc[7], x3, w01.y);
    ffma2(acc[8], x0, w23.x);  ffma2(acc[9], x1, w23.x);
    ffma2(acc[10], x2, w23.x); ffma2(acc[11], x3, w23.x);
    ffma2(acc[12], x0, w23.y); ffma2(acc[13], x1, w23.y);
    ffma2(acc[14], x2, w23.y); ffma2(acc[15], x3, w23.y);
    ffma2(acc[16], x0, w45.x); ffma2(acc[17], x1, w45.x);
    ffma2(acc[18], x2, w45.x); ffma2(acc[19], x3, w45.x);
    ffma2(acc[20], x0, w45.y); ffma2(acc[21], x1, w45.y);
    ffma2(acc[22], x2, w45.y); ffma2(acc[23], x3, w45.y);
    ffma2(acc[24], x0, w67.x); ffma2(acc[25], x1, w67.x);
    ffma2(acc[26], x2, w67.x); ffma2(acc[27], x3, w67.x);
    ffma2(acc[28], x0, w67.y); ffma2(acc[29], x1, w67.y);
    ffma2(acc[30], x2, w67.y); ffma2(acc[31], x3, w67.y);
}

__global__ void __launch_bounds__(128, 4)
conv_kernel(const float* __restrict__ x, float* __restrict__ out) {
    __shared__ __align__(16) float xs[CI_HALF * 10 * XS_STRIDE];  // 30720 B
    __shared__ __align__(16) float ws[2 * WCHUNK];                 // 16384 B

    const int tid = threadIdx.x;
    const int og = tid >> 3;  // 0..15 : o-group (8 outputs each)
    const int pg = tid & 7;   // 0..7  : output row within tile
    const int tx = blockIdx.x, ty = blockIdx.y, b = blockIdx.z;
    const int gy0 = ty * 8 - 1;
    const int gx0 = tx * 8 - 1;

    unsigned long long acc[32];
#pragma unroll
    for (int j = 0; j < 32; j++) acc[j] = 0ULL;

    int buf = 0;
    issue_chunk(ws, g_weff, tid);  // (h=0, kidx=0, ic=0)

#pragma unroll 1
    for (int h = 0; h < 2; h++) {
        // ---- stage x patch for channels [h*64, h*64+64) (pad value = 1.0) ----
        const float* xh = x + ((size_t)b * C_IN + h * CI_HALF) * HW * HW;
#pragma unroll 1
        for (int idx = tid; idx < CI_HALF * 100; idx += 128) {
            int i = idx / 100;
            int rem = idx - i * 100;
            int r = rem / 10;
            int c = rem - r * 10;
            int gy = gy0 + r, gx = gx0 + c;
            float v = 1.0f;
            if ((unsigned)gy < HW && (unsigned)gx < HW)
                v = xh[(i * HW + gy) * HW + gx];
            xs[i * (10 * XS_STRIDE) + r * XS_STRIDE + c] = v;
        }
        // visibility of xs guaranteed by the __syncthreads() before first compute below

#pragma unroll 1
        for (int kidx = 0; kidx < 9; kidx++) {
            const int ky = kidx / 3;
            const int kx = kidx - 3 * ky;
            const float* xb = xs + (pg + ky) * XS_STRIDE + kx;
#pragma unroll 1
            for (int ic = 0; ic < 8; ic++) {
                // prefetch next chunk into the other buffer
                int nic = ic + 1, nk = kidx, nh = h;
                if (nic == 8) { nic = 0; if (++nk == 9) { nk = 0; nh++; } }
                if (nh < 2) {
                    issue_chunk(ws + (buf ^ 1) * WCHUNK,
                                g_weff + ((size_t)(nk * C_IN + nh * CI_HALF + nic * KC)) *
                                             (C_OUT * 2),
                                tid);
                    asm volatile("cp.async.wait_group 1;" ::: "memory");
                } else {
                    asm volatile("cp.async.wait_group 0;" ::: "memory");
                }
                __syncthreads();

                const float* wbase = ws + buf * WCHUNK + og * 16;
                const float* xc = xb + ic * KC * (10 * XS_STRIDE);
                if (kx != 1) {
                    // 8-byte aligned packed loads (kx even)
#pragma unroll
                    for (int kk = 0; kk < KC; kk++) {
                        const float* xr = xc + kk * (10 * XS_STRIDE);
                        unsigned long long x0 = *(const unsigned long long*)(xr + 0);
                        unsigned long long x1 = *(const unsigned long long*)(xr + 2);
                        unsigned long long x2 = *(const unsigned long long*)(xr + 4);
                        unsigned long long x3 = *(const unsigned long long*)(xr + 6);
                        fma_tile(acc, x0, x1, x2, x3, wbase + kk * (C_OUT * 2));
                    }
                } else {
                    // odd offset: scalar loads + pack
#pragma unroll
                    for (int kk = 0; kk < KC; kk++) {
                        const float* xr = xc + kk * (10 * XS_STRIDE);
                        float f0 = xr[0], f1 = xr[1], f2 = xr[2], f3 = xr[3];
                        float f4 = xr[4], f5 = xr[5], f6 = xr[6], f7 = xr[7];
                        unsigned long long x0 = pack2(f0, f1);
                        unsigned long long x1 = pack2(f2, f3);
                        unsigned long long x2 = pack2(f4, f5);
                        unsigned long long x3 = pack2(f6, f7);
                        fma_tile(acc, x0, x1, x2, x3, wbase + kk * (C_OUT * 2));
                    }
                }
                __syncthreads();
                buf ^= 1;
            }
        }
    }

    // ---- epilogue: 8 o x 8 pos per thread ----
    const int oy = ty * 8 + pg;
    const int ox = tx * 8;
#pragma unroll
    for (int oo = 0; oo < 8; oo++) {
        int o = og * 8 + oo;
        float* orow = out + (((size_t)b * C_OUT + o) * HW + oy) * HW + ox;
#pragma unroll
        for (int p = 0; p < 4; p++) {
            float a, bb;
            unpack2(acc[oo * 4 + p], a, bb);
            *(float2*)(orow + 2 * p) = make_float2(a, bb);
        }
    }
}

// ================= launcher =================
extern "C" void kernel_launch(void* const* d_in, const int* in_sizes, int n_in,
                              void* d_out, int out_size) {
    const float* x = (const float*)d_in[0];        // [32,128,56,56]
    const float* w = (const float*)d_in[1];        // [5,128,128,3,3]
    const float* scales = (const float*)d_in[2];   // [5]
    float* out = (float*)d_out;                    // [32,128,56,56]

    mean_abs_kernel<<<N_BASES, 256>>>(w);
    build_weff_kernel<<<(WELEMS + 255) / 256, 256>>>(w, scales);
    conv_kernel<<<dim3(7, 7, BATCH), 128>>>(x, out);
}

// round 6
// speedup vs baseline: 1.4712x; 1.4712x over previous
#include <cuda_runtime.h>
#include <cuda_fp16.h>
#include <cstdint>

#define HW     56
#define CIN    128
#define COUT   128
#define NB     5
#define WELEMS (COUT * CIN * 9)

// ---------------- device scratch (no allocs allowed) ----------------
__device__ float g_part[40];
__device__ float g_m[NB];
// effective weights, fp16 hi/lo, pre-swizzled ldmatrix-ready tiles:
// [tap][chunk][plane(hi,lo)][k=64][n=128] ; byte off within plane = k*256 + ((n*2)^((k&7)*16))
__device__ __align__(256) __half g_wB[9 * 2 * 2 * 64 * 128];

// ---------------- helpers ----------------
static __device__ __forceinline__ uint32_t smem_u32(const void* p) {
    uint32_t a;
    asm("{ .reg .u64 t; cvta.to.shared.u64 t, %1; cvt.u32.u64 %0, t; }" : "=r"(a) : "l"(p));
    return a;
}

static __device__ __forceinline__ void mma16816(float* c, const uint32_t* a,
                                                uint32_t b0, uint32_t b1) {
    asm volatile(
        "mma.sync.aligned.m16n8k16.row.col.f32.f16.f16.f32 "
        "{%0,%1,%2,%3}, {%4,%5,%6,%7}, {%8,%9}, {%0,%1,%2,%3};"
        : "+f"(c[0]), "+f"(c[1]), "+f"(c[2]), "+f"(c[3])
        : "r"(a[0]), "r"(a[1]), "r"(a[2]), "r"(a[3]), "r"(b0), "r"(b1));
}

static __device__ __forceinline__ void ldsm4t(uint32_t* r, uint32_t addr) {
    asm volatile("ldmatrix.sync.aligned.m8n8.x4.trans.shared.b16 {%0,%1,%2,%3}, [%4];"
                 : "=r"(r[0]), "=r"(r[1]), "=r"(r[2]), "=r"(r[3])
                 : "r"(addr));
}

// ================= prep 1: partial sums of |w| (40 blocks) =================
__global__ void mean_abs_part_kernel(const float* __restrict__ w) {
    int n = blockIdx.x >> 3, seg = blockIdx.x & 7;
    const float* wn = w + (size_t)n * WELEMS + seg * (WELEMS / 8);
    float s = 0.f;
    for (int i = threadIdx.x; i < WELEMS / 8; i += 256) s += fabsf(wn[i]);
    __shared__ float red[256];
    red[threadIdx.x] = s;
    __syncthreads();
    for (int off = 128; off > 0; off >>= 1) {
        if (threadIdx.x < off) red[threadIdx.x] += red[threadIdx.x + off];
        __syncthreads();
    }
    if (threadIdx.x == 0) g_part[blockIdx.x] = red[0];
}

// ================= prep 2: finalize means =================
__global__ void mean_abs_fin_kernel() {
    int t = threadIdx.x;
    if (t < NB) {
        float s = 0.f;
        for (int i = 0; i < 8; i++) s += g_part[t * 8 + i];
        g_m[t] = s / (float)WELEMS;
    }
}

// ====== prep 3: effective weight -> swizzled fp16 hi/lo B tiles ======
__global__ void build_wB_kernel(const float* __restrict__ w,
                                const float* __restrict__ scales) {
    int idx = blockIdx.x * 256 + threadIdx.x;   // ((kidx*128 + i)*128 + o)
    if (idx >= WELEMS) return;
    int o = idx & 127;            // n (cout)
    int i = (idx >> 7) & 127;     // cin
    int kidx = idx >> 14;         // tap
    float v = 0.f;
#pragma unroll
    for (int n = 0; n < NB; n++) {
        float wv = w[(((size_t)n * COUT + o) * CIN + i) * 9 + kidx];
        float sg = (wv > 0.f) ? 1.f : ((wv < 0.f) ? -1.f : 0.f);
        v += scales[n] * g_m[n] * sg;
    }
    __half hi = __float2half_rn(v);
    __half lo = __float2half_rn(v - __half2float(hi));
    int chunk = i >> 6;
    int kl = i & 63;
    size_t tile = (size_t)(kidx * 2 + chunk) * 2 * 8192;   // in halves
    uint32_t boff = (uint32_t)kl * 256 + (((uint32_t)o * 2) ^ (((uint32_t)kl & 7) * 16));
    g_wB[tile + (boff >> 1)] = hi;
    g_wB[tile + 8192 + (boff >> 1)] = lo;
}

// ================= conv kernel (HMMA implicit GEMM) =================
// dyn smem (bytes):
//   [0]      B tiles: 2 bufs x (hi 16384 + lo 16384) = 65536
//   [65536]  slab_hi: 32 k-pair rows x 232 words + 16 pad = 7440 words = 29760
//   [95296]  slab_lo: 29760
#define SM_B      0u
#define SM_SLABH  65536u
#define SM_SLABL  95296u
#define SMEM_TOTAL 125056

static __device__ __forceinline__ void issue_B(uint32_t sdst, const uint8_t* gsrc, int tid) {
    uint32_t s = sdst + (uint32_t)tid * 16u;
    const uint8_t* g = gsrc + tid * 16;
#pragma unroll
    for (int i = 0; i < 8; i++)
        asm volatile("cp.async.cg.shared.global [%0], [%1], 16;" ::
                     "r"(s + i * 4096u), "l"(g + i * 4096));
    asm volatile("cp.async.commit_group;" ::: "memory");
}

__global__ void __launch_bounds__(256, 1)
conv_kernel(const float* __restrict__ x, float* __restrict__ out) {
    extern __shared__ __align__(16) uint8_t smem[];
    const uint32_t sb = smem_u32(smem);
    uint32_t* slabh = (uint32_t*)(smem + SM_SLABH);
    uint32_t* slabl = (uint32_t*)(smem + SM_SLABL);

    const int tid = threadIdx.x;
    const int lane = tid & 31, wid = tid >> 5;
    const int g = lane >> 2, tig = lane & 3;
    const int mw = wid & 3;          // m block of 32
    const int nw = wid >> 2;         // n block of 64
    const int r0 = blockIdx.x * 2;   // first output row
    const int b = blockIdx.y;

    // zero slab pad (finite garbage only)
    if (tid < 16) { slabh[7424 + tid] = 0; slabl[7424 + tid] = 0; }

    float acc[2][8][4];
#pragma unroll
    for (int i = 0; i < 2; i++)
#pragma unroll
        for (int j = 0; j < 8; j++)
#pragma unroll
            for (int q = 0; q < 4; q++) acc[i][j][q] = 0.f;

    // B ldmatrix lane constants
    const int krow_l = (lane & 7) + ((lane & 8) ? 8 : 0);
    const int nsel = ((lane & 16) ? 8 : 0) + nw * 64;

    issue_B(sb + SM_B, (const uint8_t*)g_wB, tid);   // iter 0 tile

#pragma unroll 1
    for (int iter = 0; iter < 18; iter++) {
        const int chunk = (iter >= 9) ? 1 : 0;
        const int kidx = iter - 9 * chunk;
        const int ky = kidx / 3;
        const int kx = kidx - 3 * ky;

        __syncthreads();   // protects B buf reuse + slab overwrite

        // stage x slab for this 64-channel chunk (constant pad = 1.0)
        if (kidx == 0) {
            const float* xp = x + ((size_t)b * CIN + chunk * 64) * (HW * HW);
#pragma unroll 1
            for (int idx = tid; idx < 64 * 232; idx += 256) {
                int ch = idx / 232;
                int pos = idx - ch * 232;
                int r = pos / 58;
                int c = pos - r * 58;
                int gy = r0 - 1 + r, gx = c - 1;
                float v = 1.0f;
                if ((unsigned)gy < HW && (unsigned)gx < HW)
                    v = __ldg(xp + ch * (HW * HW) + gy * HW + gx);
                __half hi = __float2half_rn(v);
                __half lo = __float2half_rn(v - __half2float(hi));
                int wd = (ch >> 1) * 232 + pos;
                ((__half*)slabh)[wd * 2 + (ch & 1)] = hi;
                ((__half*)slabl)[wd * 2 + (ch & 1)] = lo;
            }
        }

        // prefetch next B tile (double buffered)
        if (iter + 1 < 18) {
            int nxt = iter + 1;
            int nc = (nxt >= 9) ? 1 : 0;
            int nk = nxt - 9 * nc;
            issue_B(sb + SM_B + (uint32_t)((nxt & 1) * 32768),
                    (const uint8_t*)g_wB + (size_t)(nk * 2 + nc) * 32768, tid);
            asm volatile("cp.async.wait_group 1;" ::: "memory");
        } else {
            asm volatile("cp.async.wait_group 0;" ::: "memory");
        }
        __syncthreads();

        const uint32_t bbase = sb + SM_B + (uint32_t)((iter & 1) * 32768);

#pragma unroll
        for (int s = 0; s < 4; s++) {
            // ---- A fragments via plain LDS.32 from k-pair-packed slab ----
            uint32_t ah[2][4], al[2][4];
#pragma unroll
            for (int mb = 0; mb < 2; mb++) {
                const int mf = mw * 32 + mb * 16;
                const int pos0 = ((mf >> 6) + ky) * 58 + (mf & 63) + kx + g;
                const int w0 = (s * 8 + tig) * 232 + pos0;
                ah[mb][0] = slabh[w0];
                ah[mb][1] = slabh[w0 + 8];
                ah[mb][2] = slabh[w0 + 4 * 232];
                ah[mb][3] = slabh[w0 + 4 * 232 + 8];
                al[mb][0] = slabl[w0];
                al[mb][1] = slabl[w0 + 8];
                al[mb][2] = slabl[w0 + 4 * 232];
                al[mb][3] = slabl[w0 + 4 * 232 + 8];
            }
            const uint32_t krow = (uint32_t)(s * 16 + krow_l);
#pragma unroll
            for (int np = 0; np < 4; np++) {
                const uint32_t nn = (uint32_t)(nsel + np * 16);
                const uint32_t boff = krow * 256 + ((nn * 2) ^ ((krow & 7) * 16));
                uint32_t bh[4], bl[4];
                ldsm4t(bh, bbase + boff);
                ldsm4t(bl, bbase + 16384u + boff);
#pragma unroll
                for (int mb = 0; mb < 2; mb++) {
                    mma16816(acc[mb][np * 2],     ah[mb], bh[0], bh[1]);
                    mma16816(acc[mb][np * 2 + 1], ah[mb], bh[2], bh[3]);
                    mma16816(acc[mb][np * 2],     ah[mb], bl[0], bl[1]);
                    mma16816(acc[mb][np * 2 + 1], ah[mb], bl[2], bl[3]);
                    mma16816(acc[mb][np * 2],     al[mb], bh[0], bh[1]);
                    mma16816(acc[mb][np * 2 + 1], al[mb], bh[2], bh[3]);
                }
            }
        }
    }

    // ---- epilogue: register accumulators -> gmem ----
#pragma unroll
    for (int mb = 0; mb < 2; mb++) {
        const int mf = mw * 32 + mb * 16;
        const int y = r0 + (mf >> 6);
        const int xa = (mf & 63) + g;
        const int xb = xa + 8;
#pragma unroll
        for (int ni = 0; ni < 8; ni++) {
            const int n = nw * 64 + ni * 8 + tig * 2;
            float* p = out + ((size_t)b * COUT + n) * (HW * HW) + y * HW;
            // xa <= 55 always valid
            p[xa] = acc[mb][ni][0];
            p[HW * HW + xa] = acc[mb][ni][1];
            if (xb < HW) {
                p[xb] = acc[mb][ni][2];
                p[HW * HW + xb] = acc[mb][ni][3];
            }
        }
    }
}

// ================= launcher =================
extern "C" void kernel_launch(void* const* d_in, const int* in_sizes, int n_in,
                              void* d_out, int out_size) {
    const float* x = (const float*)d_in[0];        // [32,128,56,56]
    const float* w = (const float*)d_in[1];        // [5,128,128,3,3]
    const float* scales = (const float*)d_in[2];   // [5]
    float* out = (float*)d_out;                    // [32,128,56,56]

    cudaFuncSetAttribute(conv_kernel, cudaFuncAttributeMaxDynamicSharedMemorySize,
                         SMEM_TOTAL);

    mean_abs_part_kernel<<<40, 256>>>(w);
    mean_abs_fin_kernel<<<1, 32>>>();
    build_wB_kernel<<<(WELEMS + 255) / 256, 256>>>(w, scales);
    conv_kernel<<<dim3(28, 32), 256, SMEM_TOTAL>>>(x, out);
}

// round 7
// speedup vs baseline: 1.9176x; 1.3035x over previous
#include <cuda_runtime.h>
#include <cuda_fp16.h>
#include <cstdint>

#define HW     56
#define CIN    128
#define COUT   128
#define NB     5
#define WELEMS (COUT * CIN * 9)

// ---------------- device scratch (no allocs allowed) ----------------
__device__ float g_part[40];
__device__ float g_m[NB];
// effective weights, fp16 hi/lo, pre-swizzled ldmatrix-ready tiles:
// [tap][chunk][plane(hi,lo)][k=64][n=128] ; byte off within plane = k*256 + ((n*2)^((k&7)*16))
__device__ __align__(256) __half g_wB[9 * 2 * 2 * 64 * 128];

// ---------------- helpers ----------------
static __device__ __forceinline__ uint32_t smem_u32(const void* p) {
    uint32_t a;
    asm("{ .reg .u64 t; cvta.to.shared.u64 t, %1; cvt.u32.u64 %0, t; }" : "=r"(a) : "l"(p));
    return a;
}

static __device__ __forceinline__ void mma16816(float* c, const uint32_t* a,
                                                uint32_t b0, uint32_t b1) {
    asm volatile(
        "mma.sync.aligned.m16n8k16.row.col.f32.f16.f16.f32 "
        "{%0,%1,%2,%3}, {%4,%5,%6,%7}, {%8,%9}, {%0,%1,%2,%3};"
        : "+f"(c[0]), "+f"(c[1]), "+f"(c[2]), "+f"(c[3])
        : "r"(a[0]), "r"(a[1]), "r"(a[2]), "r"(a[3]), "r"(b0), "r"(b1));
}

static __device__ __forceinline__ void ldsm4t(uint32_t* r, uint32_t addr) {
    asm volatile("ldmatrix.sync.aligned.m8n8.x4.trans.shared.b16 {%0,%1,%2,%3}, [%4];"
                 : "=r"(r[0]), "=r"(r[1]), "=r"(r[2]), "=r"(r[3])
                 : "r"(addr));
}

// ================= prep 1: partial sums of |w| (40 blocks) =================
__global__ void mean_abs_part_kernel(const float* __restrict__ w) {
    int n = blockIdx.x >> 3, seg = blockIdx.x & 7;
    const float* wn = w + (size_t)n * WELEMS + seg * (WELEMS / 8);
    float s = 0.f;
    for (int i = threadIdx.x; i < WELEMS / 8; i += 256) s += fabsf(wn[i]);
    __shared__ float red[256];
    red[threadIdx.x] = s;
    __syncthreads();
    for (int off = 128; off > 0; off >>= 1) {
        if (threadIdx.x < off) red[threadIdx.x] += red[threadIdx.x + off];
        __syncthreads();
    }
    if (threadIdx.x == 0) g_part[blockIdx.x] = red[0];
}

// ================= prep 2: finalize means =================
__global__ void mean_abs_fin_kernel() {
    int t = threadIdx.x;
    if (t < NB) {
        float s = 0.f;
        for (int i = 0; i < 8; i++) s += g_part[t * 8 + i];
        g_m[t] = s / (float)WELEMS;
    }
}

// ====== prep 3: effective weight -> swizzled fp16 hi/lo B tiles ======
__global__ void build_wB_kernel(const float* __restrict__ w,
                                const float* __restrict__ scales) {
    int idx = blockIdx.x * 256 + threadIdx.x;   // ((kidx*128 + i)*128 + o)
    if (idx >= WELEMS) return;
    int o = idx & 127;            // n (cout)
    int i = (idx >> 7) & 127;     // cin
    int kidx = idx >> 14;         // tap
    float v = 0.f;
#pragma unroll
    for (int n = 0; n < NB; n++) {
        float wv = w[(((size_t)n * COUT + o) * CIN + i) * 9 + kidx];
        float sg = (wv > 0.f) ? 1.f : ((wv < 0.f) ? -1.f : 0.f);
        v += scales[n] * g_m[n] * sg;
    }
    __half hi = __float2half_rn(v);
    __half lo = __float2half_rn(v - __half2float(hi));
    int chunk = i >> 6;
    int kl = i & 63;
    size_t tile = (size_t)(kidx * 2 + chunk) * 2 * 8192;   // in halves
    uint32_t boff = (uint32_t)kl * 256 + (((uint32_t)o * 2) ^ (((uint32_t)kl & 7) * 16));
    g_wB[tile + (boff >> 1)] = hi;
    g_wB[tile + 8192 + (boff >> 1)] = lo;
}

// ================= conv kernel (HMMA implicit GEMM, 512 thr) =================
// dyn smem (bytes):
//   [0]      B tiles: 2 bufs x (hi 16384 + lo 16384) = 65536
//   [65536]  slab_hi: 32 k-pair rows x 232 words + 16 pad = 7440 words = 29760
//   [95296]  slab_lo: 29760
#define SM_B      0u
#define SM_SLABH  65536u
#define SM_SLABL  95296u
#define SMEM_TOTAL 125056

static __device__ __forceinline__ void issue_B(uint32_t sdst, const uint8_t* gsrc, int tid) {
    uint32_t s = sdst + (uint32_t)tid * 16u;
    const uint8_t* g = gsrc + tid * 16;
#pragma unroll
    for (int i = 0; i < 4; i++)
        asm volatile("cp.async.cg.shared.global [%0], [%1], 16;" ::
                     "r"(s + i * 8192u), "l"(g + i * 8192));
    asm volatile("cp.async.commit_group;" ::: "memory");
}

__global__ void __launch_bounds__(512, 1)
conv_kernel(const float* __restrict__ x, float* __restrict__ out) {
    extern __shared__ __align__(16) uint8_t smem[];
    const uint32_t sb = smem_u32(smem);
    uint32_t* slabh = (uint32_t*)(smem + SM_SLABH);
    uint32_t* slabl = (uint32_t*)(smem + SM_SLABL);

    const int tid = threadIdx.x;
    const int lane = tid & 31, wid = tid >> 5;
    const int g = lane >> 2, tig = lane & 3;
    const int mw = wid & 7;          // m block of 16  (8 blocks -> M=128)
    const int nw = wid >> 3;         // n half of 64   (2 halves -> N=128)
    const int mf = mw * 16;
    const int r0 = blockIdx.x * 2;   // first output row
    const int b = blockIdx.y;

    // zero slab pad (finite garbage only)
    if (tid < 16) { slabh[7424 + tid] = 0; slabl[7424 + tid] = 0; }

    float acc[8][4];
#pragma unroll
    for (int j = 0; j < 8; j++)
#pragma unroll
        for (int q = 0; q < 4; q++) acc[j][q] = 0.f;

    // B ldmatrix lane constants
    const int krow_l = (lane & 7) + ((lane & 8) ? 8 : 0);
    const int nsel = ((lane & 16) ? 8 : 0) + nw * 64;

    issue_B(sb + SM_B, (const uint8_t*)g_wB, tid);   // iter 0 tile

#pragma unroll 1
    for (int iter = 0; iter < 18; iter++) {
        const int chunk = (iter >= 9) ? 1 : 0;
        const int kidx = iter - 9 * chunk;
        const int ky = kidx / 3;
        const int kx = kidx - 3 * ky;

        __syncthreads();   // protects B buf reuse + slab overwrite

        // stage x slab for this 64-channel chunk (constant pad = 1.0)
        if (kidx == 0) {
            const float* xp = x + ((size_t)b * CIN + chunk * 64) * (HW * HW);
#pragma unroll 1
            for (int idx = tid; idx < 64 * 232; idx += 512) {
                int ch = idx / 232;
                int pos = idx - ch * 232;
                int r = pos / 58;
                int c = pos - r * 58;
                int gy = r0 - 1 + r, gx = c - 1;
                float v = 1.0f;
                if ((unsigned)gy < HW && (unsigned)gx < HW)
                    v = __ldg(xp + ch * (HW * HW) + gy * HW + gx);
                __half hi = __float2half_rn(v);
                __half lo = __float2half_rn(v - __half2float(hi));
                int wd = (ch >> 1) * 232 + pos;
                ((__half*)slabh)[wd * 2 + (ch & 1)] = hi;
                ((__half*)slabl)[wd * 2 + (ch & 1)] = lo;
            }
        }

        // prefetch next B tile (double buffered)
        if (iter + 1 < 18) {
            int nxt = iter + 1;
            int nc = (nxt >= 9) ? 1 : 0;
            int nk = nxt - 9 * nc;
            issue_B(sb + SM_B + (uint32_t)((nxt & 1) * 32768),
                    (const uint8_t*)g_wB + (size_t)(nk * 2 + nc) * 32768, tid);
            asm volatile("cp.async.wait_group 1;" ::: "memory");
        } else {
            asm volatile("cp.async.wait_group 0;" ::: "memory");
        }
        __syncthreads();

        const uint32_t bbase = sb + SM_B + (uint32_t)((iter & 1) * 32768);

#pragma unroll
        for (int s = 0; s < 4; s++) {
            // ---- A fragment via plain LDS.32 from k-pair-packed slab ----
            const int pos0 = ((mf >> 6) + ky) * 58 + (mf & 63) + kx + g;
            const int w0 = (s * 8 + tig) * 232 + pos0;
            uint32_t ah[4], al[4];
            ah[0] = slabh[w0];
            ah[1] = slabh[w0 + 8];
            ah[2] = slabh[w0 + 4 * 232];
            ah[3] = slabh[w0 + 4 * 232 + 8];
            al[0] = slabl[w0];
            al[1] = slabl[w0 + 8];
            al[2] = slabl[w0 + 4 * 232];
            al[3] = slabl[w0 + 4 * 232 + 8];

            const uint32_t krow = (uint32_t)(s * 16 + krow_l);
#pragma unroll
            for (int np = 0; np < 4; np++) {
                const uint32_t nn = (uint32_t)(nsel + np * 16);
                const uint32_t boff = krow * 256 + ((nn * 2) ^ ((krow & 7) * 16));
                uint32_t bh[4], bl[4];
                ldsm4t(bh, bbase + boff);
                ldsm4t(bl, bbase + 16384u + boff);
                mma16816(acc[np * 2],     ah, bh[0], bh[1]);
                mma16816(acc[np * 2 + 1], ah, bh[2], bh[3]);
                mma16816(acc[np * 2],     ah, bl[0], bl[1]);
                mma16816(acc[np * 2 + 1], ah, bl[2], bl[3]);
                mma16816(acc[np * 2],     al, bh[0], bh[1]);
                mma16816(acc[np * 2 + 1], al, bh[2], bh[3]);
            }
        }
    }

    // ---- epilogue: register accumulators -> gmem ----
    {
        const int y = r0 + (mf >> 6);
        const int xa = (mf & 63) + g;     // <= 55, always valid
        const int xb = xa + 8;
#pragma unroll
        for (int ni = 0; ni < 8; ni++) {
            const int n = nw * 64 + ni * 8 + tig * 2;
            float* p = out + ((size_t)b * COUT + n) * (HW * HW) + y * HW;
            p[xa] = acc[ni][0];
            p[HW * HW + xa] = acc[ni][1];
            if (xb < HW) {
                p[xb] = acc[ni][2];
                p[HW * HW + xb] = acc[ni][3];
            }
        }
    }
}

// ================= launcher =================
extern "C" void kernel_launch(void* const* d_in, const int* in_sizes, int n_in,
                              void* d_out, int out_size) {
    const float* x = (const float*)d_in[0];        // [32,128,56,56]
    const float* w = (const float*)d_in[1];        // [5,128,128,3,3]
    const float* scales = (const float*)d_in[2];   // [5]
    float* out = (float*)d_out;                    // [32,128,56,56]

    cudaFuncSetAttribute(conv_kernel, cudaFuncAttributeMaxDynamicSharedMemorySize,
                         SMEM_TOTAL);

    mean_abs_part_kernel<<<40, 256>>>(w);
    mean_abs_fin_kernel<<<1, 32>>>();
    build_wB_kernel<<<(WELEMS + 255) / 256, 256>>>(w, scales);
    conv_kernel<<<dim3(28, 32), 512, SMEM_TOTAL>>>(x, out);
}

// round 8
// speedup vs baseline: 3.4370x; 1.7923x over previous
#include <cuda_runtime.h>
#include <cuda_fp16.h>
#include <cstdint>

#define HW     56
#define CIN    128
#define COUT   128
#define NB     5
#define WELEMS (COUT * CIN * 9)

// ---------------- device scratch (no allocs allowed) ----------------
__device__ float g_part[40];
__device__ float g_m[NB];
// effective weights, fp16 hi/lo, pre-swizzled ldmatrix-ready tiles:
// [tap][chunk][plane(hi,lo)][k=64][n=128] ; byte off within plane = k*256 + ((n*2)^((k&7)*16))
__device__ __align__(256) __half g_wB[9 * 2 * 2 * 64 * 128];

// ---------------- helpers ----------------
static __device__ __forceinline__ uint32_t smem_u32(const void* p) {
    uint32_t a;
    asm("{ .reg .u64 t; cvta.to.shared.u64 t, %1; cvt.u32.u64 %0, t; }" : "=r"(a) : "l"(p));
    return a;
}

static __device__ __forceinline__ void mma16816(float* c, const uint32_t* a,
                                                uint32_t b0, uint32_t b1) {
    asm volatile(
        "mma.sync.aligned.m16n8k16.row.col.f32.f16.f16.f32 "
        "{%0,%1,%2,%3}, {%4,%5,%6,%7}, {%8,%9}, {%0,%1,%2,%3};"
        : "+f"(c[0]), "+f"(c[1]), "+f"(c[2]), "+f"(c[3])
        : "r"(a[0]), "r"(a[1]), "r"(a[2]), "r"(a[3]), "r"(b0), "r"(b1));
}

static __device__ __forceinline__ void ldsm4t(uint32_t* r, uint32_t addr) {
    asm volatile("ldmatrix.sync.aligned.m8n8.x4.trans.shared.b16 {%0,%1,%2,%3}, [%4];"
                 : "=r"(r[0]), "=r"(r[1]), "=r"(r[2]), "=r"(r[3])
                 : "r"(addr));
}

// ================= prep 1: partial sums of |w| (40 blocks) =================
__global__ void mean_abs_part_kernel(const float* __restrict__ w) {
    int n = blockIdx.x >> 3, seg = blockIdx.x & 7;
    const float* wn = w + (size_t)n * WELEMS + seg * (WELEMS / 8);
    float s = 0.f;
    for (int i = threadIdx.x; i < WELEMS / 8; i += 256) s += fabsf(wn[i]);
    __shared__ float red[256];
    red[threadIdx.x] = s;
    __syncthreads();
    for (int off = 128; off > 0; off >>= 1) {
        if (threadIdx.x < off) red[threadIdx.x] += red[threadIdx.x + off];
        __syncthreads();
    }
    if (threadIdx.x == 0) g_part[blockIdx.x] = red[0];
}

// ================= prep 2: finalize means =================
__global__ void mean_abs_fin_kernel() {
    int t = threadIdx.x;
    if (t < NB) {
        float s = 0.f;
        for (int i = 0; i < 8; i++) s += g_part[t * 8 + i];
        g_m[t] = s / (float)WELEMS;
    }
}

// ====== prep 3: effective weight -> swizzled fp16 hi/lo B tiles ======
__global__ void build_wB_kernel(const float* __restrict__ w,
                                const float* __restrict__ scales) {
    int idx = blockIdx.x * 256 + threadIdx.x;   // ((kidx*128 + i)*128 + o)
    if (idx >= WELEMS) return;
    int o = idx & 127;            // n (cout)
    int i = (idx >> 7) & 127;     // cin
    int kidx = idx >> 14;         // tap
    float v = 0.f;
#pragma unroll
    for (int n = 0; n < NB; n++) {
        float wv = w[(((size_t)n * COUT + o) * CIN + i) * 9 + kidx];
        float sg = (wv > 0.f) ? 1.f : ((wv < 0.f) ? -1.f : 0.f);
        v += scales[n] * g_m[n] * sg;
    }
    __half hi = __float2half_rn(v);
    __half lo = __float2half_rn(v - __half2float(hi));
    int chunk = i >> 6;
    int kl = i & 63;
    size_t tile = (size_t)(kidx * 2 + chunk) * 2 * 8192;   // in halves
    uint32_t boff = (uint32_t)kl * 256 + (((uint32_t)o * 2) ^ (((uint32_t)kl & 7) * 16));
    g_wB[tile + (boff >> 1)] = hi;
    g_wB[tile + 8192 + (boff >> 1)] = lo;
}

// ======= conv kernel (HMMA implicit GEMM, 512 thr, 2 CTA/SM, 2-product) =======
// dyn smem (bytes):
//   [0]      B tiles: 2 bufs x (hi 16384 + lo 16384) = 65536
//   [65536]  slab_hi: 32 k-pair rows x 232 words + 16 pad = 7440 words = 29760
#define SM_B      0u
#define SM_SLABH  65536u
#define SMEM_TOTAL 95360

static __device__ __forceinline__ void issue_B(uint32_t sdst, const uint8_t* gsrc, int tid) {
    uint32_t s = sdst + (uint32_t)tid * 16u;
    const uint8_t* g = gsrc + tid * 16;
#pragma unroll
    for (int i = 0; i < 4; i++)
        asm volatile("cp.async.cg.shared.global [%0], [%1], 16;" ::
                     "r"(s + i * 8192u), "l"(g + i * 8192));
    asm volatile("cp.async.commit_group;" ::: "memory");
}

__global__ void __launch_bounds__(512, 2)
conv_kernel(const float* __restrict__ x, float* __restrict__ out) {
    extern __shared__ __align__(16) uint8_t smem[];
    const uint32_t sb = smem_u32(smem);
    uint32_t* slabh = (uint32_t*)(smem + SM_SLABH);

    const int tid = threadIdx.x;
    const int lane = tid & 31, wid = tid >> 5;
    const int g = lane >> 2, tig = lane & 3;
    const int mw = wid & 7;          // m block of 16  (8 blocks -> M=128)
    const int nw = wid >> 3;         // n half of 64   (2 halves -> N=128)
    const int mf = mw * 16;
    const int r0 = blockIdx.x * 2;   // first output row
    const int b = blockIdx.y;

    // zero slab pad (finite garbage only)
    if (tid < 16) slabh[7424 + tid] = 0;

    float acc[8][4];
#pragma unroll
    for (int j = 0; j < 8; j++)
#pragma unroll
        for (int q = 0; q < 4; q++) acc[j][q] = 0.f;

    // B ldmatrix lane constants
    const int krow_l = (lane & 7) + ((lane & 8) ? 8 : 0);
    const int nsel = ((lane & 16) ? 8 : 0) + nw * 64;

    issue_B(sb + SM_B, (const uint8_t*)g_wB, tid);   // iter 0 tile

#pragma unroll 1
    for (int iter = 0; iter < 18; iter++) {
        const int chunk = (iter >= 9) ? 1 : 0;
        const int kidx = iter - 9 * chunk;
        const int ky = kidx / 3;
        const int kx = kidx - 3 * ky;

        __syncthreads();   // protects B buf reuse + slab overwrite

        // stage x slab for this 64-channel chunk (constant pad = 1.0), hi plane only
        if (kidx == 0) {
            const float* xp = x + ((size_t)b * CIN + chunk * 64) * (HW * HW);
#pragma unroll 1
            for (int idx = tid; idx < 64 * 232; idx += 512) {
                int ch = idx / 232;
                int pos = idx - ch * 232;
                int r = pos / 58;
                int c = pos - r * 58;
                int gy = r0 - 1 + r, gx = c - 1;
                float v = 1.0f;
                if ((unsigned)gy < HW && (unsigned)gx < HW)
                    v = __ldg(xp + ch * (HW * HW) + gy * HW + gx);
                int wd = (ch >> 1) * 232 + pos;
                ((__half*)slabh)[wd * 2 + (ch & 1)] = __float2half_rn(v);
            }
        }

        // prefetch next B tile (double buffered)
        if (iter + 1 < 18) {
            int nxt = iter + 1;
            int nc = (nxt >= 9) ? 1 : 0;
            int nk = nxt - 9 * nc;
            issue_B(sb + SM_B + (uint32_t)((nxt & 1) * 32768),
                    (const uint8_t*)g_wB + (size_t)(nk * 2 + nc) * 32768, tid);
            asm volatile("cp.async.wait_group 1;" ::: "memory");
        } else {
            asm volatile("cp.async.wait_group 0;" ::: "memory");
        }
        __syncthreads();

        const uint32_t bbase = sb + SM_B + (uint32_t)((iter & 1) * 32768);

#pragma unroll
        for (int s = 0; s < 4; s++) {
            // ---- A fragment (hi only) via plain LDS.32 from k-pair-packed slab ----
            const int pos0 = ((mf >> 6) + ky) * 58 + (mf & 63) + kx + g;
            const int w0 = (s * 8 + tig) * 232 + pos0;
            uint32_t ah[4];
            ah[0] = slabh[w0];
            ah[1] = slabh[w0 + 8];
            ah[2] = slabh[w0 + 4 * 232];
            ah[3] = slabh[w0 + 4 * 232 + 8];

            const uint32_t krow = (uint32_t)(s * 16 + krow_l);
#pragma unroll
            for (int np = 0; np < 4; np++) {
                const uint32_t nn = (uint32_t)(nsel + np * 16);
                const uint32_t boff = krow * 256 + ((nn * 2) ^ ((krow & 7) * 16));
                uint32_t bh[4], bl[4];
                ldsm4t(bh, bbase + boff);
                ldsm4t(bl, bbase + 16384u + boff);
                mma16816(acc[np * 2],     ah, bh[0], bh[1]);
                mma16816(acc[np * 2 + 1], ah, bh[2], bh[3]);
                mma16816(acc[np * 2],     ah, bl[0], bl[1]);
                mma16816(acc[np * 2 + 1], ah, bl[2], bl[3]);
            }
        }
    }

    // ---- epilogue: register accumulators -> gmem ----
    {
        const int y = r0 + (mf >> 6);
        const int xa = (mf & 63) + g;     // <= 55, always valid
        const int xb = xa + 8;
#pragma unroll
        for (int ni = 0; ni < 8; ni++) {
            const int n = nw * 64 + ni * 8 + tig * 2;
            float* p = out + ((size_t)b * COUT + n) * (HW * HW) + y * HW;
            p[xa] = acc[ni][0];
            p[HW * HW + xa] = acc[ni][1];
            if (xb < HW) {
                p[xb] = acc[ni][2];
                p[HW * HW + xb] = acc[ni][3];
            }
        }
    }
}

// ================= launcher =================
extern "C" void kernel_launch(void* const* d_in, const int* in_sizes, int n_in,
                              void* d_out, int out_size) {
    const float* x = (const float*)d_in[0];        // [32,128,56,56]
    const float* w = (const float*)d_in[1];        // [5,128,128,3,3]
    const float* scales = (const float*)d_in[2];   // [5]
    float* out = (float*)d_out;                    // [32,128,56,56]

    cudaFuncSetAttribute(conv_kernel, cudaFuncAttributeMaxDynamicSharedMemorySize,
                         SMEM_TOTAL);

    mean_abs_part_kernel<<<40, 256>>>(w);
    mean_abs_fin_kernel<<<1, 32>>>();
    build_wB_kernel<<<(WELEMS + 255) / 256, 256>>>(w, scales);
    conv_kernel<<<dim3(28, 32), 512, SMEM_TOTAL>>>(x, out);
}

// round 9
// speedup vs baseline: 4.3745x; 1.2727x over previous
#include <cuda_runtime.h>
#include <cuda_fp16.h>
#include <cstdint>

#define HW     56
#define CIN    128
#define COUT   128
#define NB     5
#define WELEMS (COUT * CIN * 9)

// ---------------- device scratch (no allocs allowed) ----------------
__device__ float g_part[40];
__device__ float g_m[NB];
// effective weights, fp16 (hi plane only), pre-swizzled ldmatrix-ready tiles:
// [tap][chunk][k=64][n=128] ; byte off within tile = k*256 + ((n*2)^((k&7)*16))
__device__ __align__(256) __half g_wB[9 * 2 * 64 * 128];

// ---------------- helpers ----------------
static __device__ __forceinline__ uint32_t smem_u32(const void* p) {
    uint32_t a;
    asm("{ .reg .u64 t; cvta.to.shared.u64 t, %1; cvt.u32.u64 %0, t; }" : "=r"(a) : "l"(p));
    return a;
}

static __device__ __forceinline__ void mma16816(float* c, const uint32_t* a,
                                                uint32_t b0, uint32_t b1) {
    asm volatile(
        "mma.sync.aligned.m16n8k16.row.col.f32.f16.f16.f32 "
        "{%0,%1,%2,%3}, {%4,%5,%6,%7}, {%8,%9}, {%0,%1,%2,%3};"
        : "+f"(c[0]), "+f"(c[1]), "+f"(c[2]), "+f"(c[3])
        : "r"(a[0]), "r"(a[1]), "r"(a[2]), "r"(a[3]), "r"(b0), "r"(b1));
}

static __device__ __forceinline__ void ldsm4t(uint32_t* r, uint32_t addr) {
    asm volatile("ldmatrix.sync.aligned.m8n8.x4.trans.shared.b16 {%0,%1,%2,%3}, [%4];"
                 : "=r"(r[0]), "=r"(r[1]), "=r"(r[2]), "=r"(r[3])
                 : "r"(addr));
}

// ================= prep 1: partial sums of |w| (40 blocks) =================
__global__ void mean_abs_part_kernel(const float* __restrict__ w) {
    int n = blockIdx.x >> 3, seg = blockIdx.x & 7;
    const float* wn = w + (size_t)n * WELEMS + seg * (WELEMS / 8);
    float s = 0.f;
    for (int i = threadIdx.x; i < WELEMS / 8; i += 256) s += fabsf(wn[i]);
    __shared__ float red[256];
    red[threadIdx.x] = s;
    __syncthreads();
    for (int off = 128; off > 0; off >>= 1) {
        if (threadIdx.x < off) red[threadIdx.x] += red[threadIdx.x + off];
        __syncthreads();
    }
    if (threadIdx.x == 0) g_part[blockIdx.x] = red[0];
}

// ================= prep 2: finalize means =================
__global__ void mean_abs_fin_kernel() {
    int t = threadIdx.x;
    if (t < NB) {
        float s = 0.f;
        for (int i = 0; i < 8; i++) s += g_part[t * 8 + i];
        g_m[t] = s / (float)WELEMS;
    }
}

// ====== prep 3: effective weight -> swizzled fp16 B tiles (hi only) ======
__global__ void build_wB_kernel(const float* __restrict__ w,
                                const float* __restrict__ scales) {
    int idx = blockIdx.x * 256 + threadIdx.x;   // ((kidx*128 + i)*128 + o)
    if (idx >= WELEMS) return;
    int o = idx & 127;            // n (cout)
    int i = (idx >> 7) & 127;     // cin
    int kidx = idx >> 14;         // tap
    float v = 0.f;
#pragma unroll
    for (int n = 0; n < NB; n++) {
        float wv = w[(((size_t)n * COUT + o) * CIN + i) * 9 + kidx];
        float sg = (wv > 0.f) ? 1.f : ((wv < 0.f) ? -1.f : 0.f);
        v += scales[n] * g_m[n] * sg;
    }
    int chunk = i >> 6;
    int kl = i & 63;
    size_t tile = (size_t)(kidx * 2 + chunk) * 8192;   // in halves
    uint32_t boff = (uint32_t)kl * 256 + (((uint32_t)o * 2) ^ (((uint32_t)kl & 7) * 16));
    g_wB[tile + (boff >> 1)] = __float2half_rn(v);
}

// ===== conv kernel (HMMA implicit GEMM, 512 thr, 2 CTA/SM, single product) =====
// dyn smem (bytes):
//   [0]      B tiles: 2 bufs x 16384 = 32768
//   [32768]  slab_hi: 32 k-pair rows x 232 words + 16 pad = 7440 words = 29760
#define SM_B      0u
#define SM_SLABH  32768u
#define SMEM_TOTAL 62528

static __device__ __forceinline__ void issue_B(uint32_t sdst, const uint8_t* gsrc, int tid) {
    uint32_t s = sdst + (uint32_t)tid * 32u;
    const uint8_t* g = gsrc + tid * 32;
    asm volatile("cp.async.cg.shared.global [%0], [%1], 16;" :: "r"(s), "l"(g));
    asm volatile("cp.async.cg.shared.global [%0], [%1], 16;" :: "r"(s + 16u), "l"(g + 16));
    asm volatile("cp.async.commit_group;" ::: "memory");
}

__global__ void __launch_bounds__(512, 2)
conv_kernel(const float* __restrict__ x, float* __restrict__ out) {
    extern __shared__ __align__(16) uint8_t smem[];
    const uint32_t sb = smem_u32(smem);
    uint32_t* slabh = (uint32_t*)(smem + SM_SLABH);

    const int tid = threadIdx.x;
    const int lane = tid & 31, wid = tid >> 5;
    const int g = lane >> 2, tig = lane & 3;
    const int mw = wid & 7;          // m block of 16  (8 blocks -> M=128)
    const int nw = wid >> 3;         // n half of 64   (2 halves -> N=128)
    const int mf = mw * 16;
    const int r0 = blockIdx.x * 2;   // first output row
    const int b = blockIdx.y;

    // zero slab pad (finite garbage only)
    if (tid < 16) slabh[7424 + tid] = 0;

    float acc[8][4];
#pragma unroll
    for (int j = 0; j < 8; j++)
#pragma unroll
        for (int q = 0; q < 4; q++) acc[j][q] = 0.f;

    // B ldmatrix lane constants
    const int krow_l = (lane & 7) + ((lane & 8) ? 8 : 0);
    const int nsel = ((lane & 16) ? 8 : 0) + nw * 64;

    issue_B(sb + SM_B, (const uint8_t*)g_wB, tid);   // iter 0 tile

#pragma unroll 1
    for (int iter = 0; iter < 18; iter++) {
        const int chunk = (iter >= 9) ? 1 : 0;
        const int kidx = iter - 9 * chunk;
        const int ky = kidx / 3;
        const int kx = kidx - 3 * ky;

        __syncthreads();   // protects B buf reuse + slab overwrite

        // stage x slab for this 64-channel chunk (constant pad = 1.0)
        if (kidx == 0) {
            const float* xp = x + ((size_t)b * CIN + chunk * 64) * (HW * HW);
#pragma unroll 1
            for (int idx = tid; idx < 64 * 232; idx += 512) {
                int ch = idx / 232;
                int pos = idx - ch * 232;
                int r = pos / 58;
                int c = pos - r * 58;
                int gy = r0 - 1 + r, gx = c - 1;
                float v = 1.0f;
                if ((unsigned)gy < HW && (unsigned)gx < HW)
                    v = __ldg(xp + ch * (HW * HW) + gy * HW + gx);
                int wd = (ch >> 1) * 232 + pos;
                ((__half*)slabh)[wd * 2 + (ch & 1)] = __float2half_rn(v);
            }
        }

        // prefetch next B tile (double buffered)
        if (iter + 1 < 18) {
            int nxt = iter + 1;
            int nc = (nxt >= 9) ? 1 : 0;
            int nk = nxt - 9 * nc;
            issue_B(sb + SM_B + (uint32_t)((nxt & 1) * 16384),
                    (const uint8_t*)g_wB + (size_t)(nk * 2 + nc) * 16384, tid);
            asm volatile("cp.async.wait_group 1;" ::: "memory");
        } else {
            asm volatile("cp.async.wait_group 0;" ::: "memory");
        }
        __syncthreads();

        const uint32_t bbase = sb + SM_B + (uint32_t)((iter & 1) * 16384);

#pragma unroll
        for (int s = 0; s < 4; s++) {
            // ---- A fragment via plain LDS.32 from k-pair-packed slab ----
            const int pos0 = ((mf >> 6) + ky) * 58 + (mf & 63) + kx + g;
            const int w0 = (s * 8 + tig) * 232 + pos0;
            uint32_t ah[4];
            ah[0] = slabh[w0];
            ah[1] = slabh[w0 + 8];
            ah[2] = slabh[w0 + 4 * 232];
            ah[3] = slabh[w0 + 4 * 232 + 8];

            const uint32_t krow = (uint32_t)(s * 16 + krow_l);
#pragma unroll
            for (int np = 0; np < 4; np++) {
                const uint32_t nn = (uint32_t)(nsel + np * 16);
                const uint32_t boff = krow * 256 + ((nn * 2) ^ ((krow & 7) * 16));
                uint32_t bh[4];
                ldsm4t(bh, bbase + boff);
                mma16816(acc[np * 2],     ah, bh[0], bh[1]);
                mma16816(acc[np * 2 + 1], ah, bh[2], bh[3]);
            }
        }
    }

    // ---- epilogue: register accumulators -> gmem ----
    {
        const int y = r0 + (mf >> 6);
        const int xa = (mf & 63) + g;     // <= 55, always valid
        const int xb = xa + 8;
#pragma unroll
        for (int ni = 0; ni < 8; ni++) {
            const int n = nw * 64 + ni * 8 + tig * 2;
            float* p = out + ((size_t)b * COUT + n) * (HW * HW) + y * HW;
            p[xa] = acc[ni][0];
            p[HW * HW + xa] = acc[ni][1];
            if (xb < HW) {
                p[xb] = acc[ni][2];
                p[HW * HW + xb] = acc[ni][3];
            }
        }
    }
}

// ================= launcher =================
extern "C" void kernel_launch(void* const* d_in, const int* in_sizes, int n_in,
                              void* d_out, int out_size) {
    const float* x = (const float*)d_in[0];        // [32,128,56,56]
    const float* w = (const float*)d_in[1];        // [5,128,128,3,3]
    const float* scales = (const float*)d_in[2];   // [5]
    float* out = (float*)d_out;                    // [32,128,56,56]

    cudaFuncSetAttribute(conv_kernel, cudaFuncAttributeMaxDynamicSharedMemorySize,
                         SMEM_TOTAL);

    mean_abs_part_kernel<<<40, 256>>>(w);
    mean_abs_fin_kernel<<<1, 32>>>();
    build_wB_kernel<<<(WELEMS + 255) / 256, 256>>>(w, scales);
    conv_kernel<<<dim3(28, 32), 512, SMEM_TOTAL>>>(x, out);
}